// round 13
// baseline (speedup 1.0000x reference)
#include <cuda_runtime.h>
#include <cuda_fp16.h>
#include <cstdint>
#include <math.h>

// ---------------- problem constants ----------------
#define B_   4
#define CIN  128
#define COUT 256
#define H_   128
#define W_   256
#define HW   (H_ * W_)              // 32768
#define TILE_M 128                  // pixels per CTA
#define NTILES (B_ * HW / TILE_M)   // 1024
#define NTHREADS 512

// ---------------- device scratch ----------------
__device__ __half g_xh[(size_t)B_ * HW * CIN];       // 32 MB (B, HW, Cin) fp16
__device__ unsigned char g_Wf16[9 * 65536];          // per tap: 256 co x 256B (128 fp16), swizzled
__device__ int4   g_tabI[9 * HW];                    // gather indices (uint2 units into g_xh)
__device__ float4 g_tabW[9 * HW];                    // bilinear weights (edge-zeroed)

// ---------------- smem layout (1024-aligned base) ----------------
#define SM_A0   0            // 128 rows x 256B = 32KB
#define SM_A1   32768        // 32KB
#define SM_W0   65536        // 64KB
#define SM_W1   131072       // 64KB
#define SM_BIAS 196608       // 1KB
#define SM_TOTAL (197632 + 1024)
// epilogue reuses [0, 128KB) as Dsm[co][px] fp32

__device__ __forceinline__ uint32_t bswz(uint32_t row, uint32_t col) {
    return col ^ ((row & 7u) << 4);
}

__device__ __forceinline__ uint32_t smem_u32(const void* p) {
    uint32_t a;
    asm("{ .reg .u64 t; cvta.to.shared.u64 t, %1; cvt.u32.u64 %0, t; }" : "=r"(a) : "l"(p));
    return a;
}

__device__ __forceinline__ void ldm_x4(uint32_t& r0, uint32_t& r1, uint32_t& r2, uint32_t& r3,
                                       uint32_t addr) {
    asm volatile("ldmatrix.sync.aligned.m8n8.x4.shared.b16 {%0,%1,%2,%3}, [%4];"
                 : "=r"(r0), "=r"(r1), "=r"(r2), "=r"(r3) : "r"(addr));
}

__device__ __forceinline__ void mma_16816(float& c0, float& c1, float& c2, float& c3,
                                          uint32_t a0, uint32_t a1, uint32_t a2, uint32_t a3,
                                          uint32_t b0, uint32_t b1) {
    asm volatile(
        "mma.sync.aligned.m16n8k16.row.col.f32.f16.f16.f32 "
        "{%0,%1,%2,%3}, {%4,%5,%6,%7}, {%8,%9}, {%0,%1,%2,%3};"
        : "+f"(c0), "+f"(c1), "+f"(c2), "+f"(c3)
        : "r"(a0), "r"(a1), "r"(a2), "r"(a3), "r"(b0), "r"(b1));
}

__device__ __forceinline__ void cp_async16(uint32_t dst, const void* src) {
    asm volatile("cp.async.cg.shared.global [%0], [%1], 16;" :: "r"(dst), "l"(src) : "memory");
}
__device__ __forceinline__ void cp_commit() {
    asm volatile("cp.async.commit_group;" ::: "memory");
}
__device__ __forceinline__ void cp_wait0() {
    asm volatile("cp.async.wait_group 0;" ::: "memory");
}

// stage a 64KB pre-swizzled W block with 512 threads, non-blocking
__device__ __forceinline__ void stageW_async(uint32_t smem_dst, const unsigned char* src, int tid) {
#pragma unroll
    for (int i = 0; i < 8; ++i) {
        cp_async16(smem_dst + i * 8192 + tid * 16, src + i * 8192 + tid * 16);
    }
}

// ---------------------------------------------------------------------------
// Kernel 1: transpose+convert x (B, Cin, H, W) fp32 -> g_xh (B, HW, Cin) fp16
// Tile: 32 cin x 128 px. float4 global loads, half8 (uint4) global stores.
// ---------------------------------------------------------------------------
__global__ void transpose_x_kernel(const float* __restrict__ x) {
    __shared__ float tile[32][129];
    const int b    = blockIdx.z;
    const int cin0 = blockIdx.y * 32;
    const int p0   = blockIdx.x * 128;
    const int tid  = threadIdx.x;              // 0..255

    // load: 32 rows (cin) x 32 float4 (128 px) = 1024 float4, 4 per thread
#pragma unroll
    for (int j = 0; j < 4; ++j) {
        const int row  = j * 8 + (tid >> 5);
        const int col4 = tid & 31;
        const float4 v = *(const float4*)(x + ((size_t)b * CIN + (cin0 + row)) * HW + p0 + col4 * 4);
        tile[row][col4 * 4 + 0] = v.x;
        tile[row][col4 * 4 + 1] = v.y;
        tile[row][col4 * 4 + 2] = v.z;
        tile[row][col4 * 4 + 3] = v.w;
    }
    __syncthreads();

    // store: 128 px x 4 cin-groups (8 cin each) = 512 uint4, 2 per thread
#pragma unroll
    for (int j = 0; j < 2; ++j) {
        const int idx = j * 256 + tid;
        const int p   = idx >> 2;
        const int c8  = idx & 3;
        __half h[8];
#pragma unroll
        for (int k = 0; k < 8; ++k)
            h[k] = __float2half(tile[c8 * 8 + k][p]);
        *(uint4*)(g_xh + ((size_t)b * HW + (p0 + p)) * CIN + cin0 + c8 * 8) = *(const uint4*)h;
    }
}

// ---------------------------------------------------------------------------
// Kernel 2: fused prep. idx < 9*32768 covers BOTH:
//  (a) weight elem (tap, co, cin) -> g_Wf16 swizzled fp16
//  (b) grid elem (tap, pixel) -> g_tabI / g_tabW
// ---------------------------------------------------------------------------
__global__ void prep_kernel(const float* __restrict__ wsrc,
                            const float* __restrict__ gridp) {
    const int idx = blockIdx.x * 256 + threadIdx.x;
    if (idx >= 9 * 32768) return;

    // ---- weight part: idx -> (t, co, cin) ----
    {
        const int cin = idx & 127;
        const int co  = (idx >> 7) & 255;
        const int t   = idx >> 15;
        const float v = wsrc[(co * CIN + cin) * 9 + t];
        const uint32_t off = (uint32_t)co * 256 + bswz(co, (uint32_t)cin * 2);
        *(__half*)(g_Wf16 + (size_t)t * 65536 + off) = __float2half(v);
    }

    // ---- grid part: idx -> (t, p) ----
    {
        const int p = idx & (HW - 1);
        const int t = idx >> 15;
        const int h = p >> 8;
        const int w = p & 255;
        const int r = t / 3;
        const int c = t - r * 3;

        const int gi = (h * 3 + r) * (W_ * 3) + (w * 3 + c);
        const float gx = gridp[2 * gi + 0];
        const float gy = gridp[2 * gi + 1];

        const float ix = ((gx + 1.0f) * (float)W_ - 1.0f) * 0.5f;
        const float iy = ((gy + 1.0f) * (float)H_ - 1.0f) * 0.5f;
        const float x0f = floorf(ix), y0f = floorf(iy);
        const float fx = ix - x0f, fy = iy - y0f;
        const int xx0 = (int)x0f, yy0 = (int)y0f;
        const int xx1 = xx0 + 1, yy1 = yy0 + 1;

        float w00 = (1.0f - fx) * (1.0f - fy);
        float w10 = fx * (1.0f - fy);
        float w01 = (1.0f - fx) * fy;
        float w11 = fx * fy;
        if (xx0 < 0 || xx0 >= W_) { w00 = 0.0f; w01 = 0.0f; }
        if (xx1 < 0 || xx1 >= W_) { w10 = 0.0f; w11 = 0.0f; }
        if (yy0 < 0 || yy0 >= H_) { w00 = 0.0f; w10 = 0.0f; }
        if (yy1 < 0 || yy1 >= H_) { w01 = 0.0f; w11 = 0.0f; }

        const int xi0 = min(max(xx0, 0), W_ - 1);
        const int xi1 = min(max(xx1, 0), W_ - 1);
        const int yi0 = min(max(yy0, 0), H_ - 1);
        const int yi1 = min(max(yy1, 0), H_ - 1);

        int4 e;
        e.x = (yi0 * W_ + xi0) * 32;
        e.y = (yi0 * W_ + xi1) * 32;
        e.z = (yi1 * W_ + xi0) * 32;
        e.w = (yi1 * W_ + xi1) * 32;
        g_tabI[idx] = e;
        g_tabW[idx] = make_float4(w00, w10, w01, w11);
    }
}

// ---------------------------------------------------------------------------
// fused tap: 8 k-steps; per k-step: gather LDGs for 1 px/warp, A frags (2 ldm),
// then np-inner loop (1 B ldm -> 4 MMAs) to keep live fragment regs low so
// ptxas can overlap LDSM latency under HMMA; blend+STS after the MMAs.
// ---------------------------------------------------------------------------
template <bool GATHER>
__device__ __forceinline__ void mma_tap_fused(
    uint32_t Abase, uint32_t Wbase, float (*acc)[8][4],
    const int4* __restrict__ tI, const float4* __restrict__ tW,
    const uint2* __restrict__ xh2, char* __restrict__ Anxt,
    uint32_t a_row_in_warp, uint32_t a_koff,
    uint32_t b_n_in_pair, uint32_t b_koff,
    int warp_m, int warp_n, int lane, int warp) {

    int4 e;
    float4 wv;
    if (GATHER) {           // table entry for pixel of k-step 0
        e  = __ldg(tI + warp);
        wv = __ldg(tW + warp);
    }

#pragma unroll
    for (int k0 = 0; k0 < 8; ++k0) {
        // ---- issue gather LDGs for pixel (k0*16 + warp) ----
        uint2 u00, u10, u01, u11;
        if (GATHER) {
            u00 = __ldg(xh2 + e.x + lane);
            u10 = __ldg(xh2 + e.y + lane);
            u01 = __ldg(xh2 + e.z + lane);
            u11 = __ldg(xh2 + e.w + lane);
        }

        const uint32_t kb = (uint32_t)k0 * 32;

        // ---- A fragments (2 ldm) ----
        uint32_t a0[2], a1[2], a2[2], a3[2];
#pragma unroll
        for (int mi = 0; mi < 2; ++mi) {
            const uint32_t row = (uint32_t)(warp_m * 32 + mi * 16) + a_row_in_warp;
            const uint32_t addr = Abase + row * 256 + bswz(row, kb + a_koff);
            ldm_x4(a0[mi], a1[mi], a2[mi], a3[mi], addr);
        }

        // ---- prefetch next table entry (consumed next k-step) ----
        int4 en;
        float4 wvn;
        if (GATHER && k0 < 7) {
            en  = __ldg(tI + (k0 + 1) * 16 + warp);
            wvn = __ldg(tW + (k0 + 1) * 16 + warp);
        }

        // ---- np-inner: load one B pair, run its 4 MMAs ----
#pragma unroll
        for (int np = 0; np < 4; ++np) {
            uint32_t b0, b1, b2, b3;
            const uint32_t n = (uint32_t)(warp_n * 64 + np * 16) + b_n_in_pair;
            const uint32_t addr = Wbase + n * 256 + bswz(n, kb + b_koff);
            ldm_x4(b0, b1, b2, b3, addr);
#pragma unroll
            for (int mi = 0; mi < 2; ++mi) {
                mma_16816(acc[mi][np * 2][0], acc[mi][np * 2][1],
                          acc[mi][np * 2][2], acc[mi][np * 2][3],
                          a0[mi], a1[mi], a2[mi], a3[mi], b0, b1);
                mma_16816(acc[mi][np * 2 + 1][0], acc[mi][np * 2 + 1][1],
                          acc[mi][np * 2 + 1][2], acc[mi][np * 2 + 1][3],
                          a0[mi], a1[mi], a2[mi], a3[mi], b2, b3);
            }
        }

        // ---- blend + store gathered pixel ----
        if (GATHER) {
            const float2 a00 = __half22float2(*(const __half2*)&u00.x);
            const float2 b00 = __half22float2(*(const __half2*)&u00.y);
            const float2 a10 = __half22float2(*(const __half2*)&u10.x);
            const float2 b10 = __half22float2(*(const __half2*)&u10.y);
            const float2 a01 = __half22float2(*(const __half2*)&u01.x);
            const float2 b01 = __half22float2(*(const __half2*)&u01.y);
            const float2 a11 = __half22float2(*(const __half2*)&u11.x);
            const float2 b11 = __half22float2(*(const __half2*)&u11.y);

            float2 s0, s1;
            s0.x = wv.x * a00.x + wv.y * a10.x + wv.z * a01.x + wv.w * a11.x;
            s0.y = wv.x * a00.y + wv.y * a10.y + wv.z * a01.y + wv.w * a11.y;
            s1.x = wv.x * b00.x + wv.y * b10.x + wv.z * b01.x + wv.w * b11.x;
            s1.y = wv.x * b00.y + wv.y * b10.y + wv.z * b01.y + wv.w * b11.y;

            const __half2 h0 = __float22half2_rn(s0);
            const __half2 h1 = __float22half2_rn(s1);

            const int pp = k0 * 16 + warp;
            const uint32_t off = (uint32_t)pp * 256 + bswz((uint32_t)pp, (uint32_t)lane * 8);
            *(uint2*)(Anxt + off) =
                make_uint2(*(const uint32_t*)&h0, *(const uint32_t*)&h1);

            e = en;
            wv = wvn;
        }
    }
}

// ---------------------------------------------------------------------------
// Kernel 3: fused gather+mma, 512 threads / 16 warps, warp tile 32x64
// ---------------------------------------------------------------------------
__global__ __launch_bounds__(NTHREADS, 1)
void sphere_hmma_kernel(const float* __restrict__ bias,
                        float* __restrict__ out) {
    extern __shared__ char dsm[];
    const uint32_t raw = smem_u32(dsm);
    const uint32_t sb  = (raw + 1023u) & ~1023u;
    char* const smp = dsm + (sb - raw);

    const int tid  = threadIdx.x;
    const int lane = tid & 31;
    const int warp = tid >> 5;          // 0..15
    const int warp_m = warp >> 2;       // 0..3
    const int warp_n = warp & 3;        // 0..3
    const int tile = blockIdx.x;
    const int b    = tile >> 8;
    const int p0   = (tile & 255) * TILE_M;

    if (tid < 256) ((float*)(smp + SM_BIAS))[tid] = bias[tid];

    const uint2* __restrict__ xh2 =
        (const uint2*)(g_xh + (size_t)b * HW * CIN);

    float acc[2][8][4];
#pragma unroll
    for (int mi = 0; mi < 2; ++mi)
#pragma unroll
        for (int ni = 0; ni < 8; ++ni)
#pragma unroll
            for (int q = 0; q < 4; ++q) acc[mi][ni][q] = 0.0f;

    const uint32_t a_row_in_warp = (uint32_t)(lane & 15);
    const uint32_t a_koff        = (uint32_t)((lane >> 4) << 4);
    const uint32_t b_n_in_pair   = (uint32_t)(((lane >> 4) & 1) * 8 + (lane & 7));
    const uint32_t b_koff        = (uint32_t)(((lane >> 3) & 1) << 4);

    // ---- prologue: stage W(0); gather A(0) (table-driven, unfused) ----
    stageW_async(sb + SM_W0, g_Wf16, tid);
    cp_commit();
    {
        const int4*   __restrict__ tI = g_tabI + p0;
        const float4* __restrict__ tW = g_tabW + p0;
#pragma unroll 2
        for (int i = 0; i < 8; ++i) {
            const int pp = i * 16 + warp;
            const int4   e  = __ldg(tI + pp);
            const float4 wv = __ldg(tW + pp);
            const uint2 u00 = __ldg(xh2 + e.x + lane);
            const uint2 u10 = __ldg(xh2 + e.y + lane);
            const uint2 u01 = __ldg(xh2 + e.z + lane);
            const uint2 u11 = __ldg(xh2 + e.w + lane);
            const float2 a00 = __half22float2(*(const __half2*)&u00.x);
            const float2 b00 = __half22float2(*(const __half2*)&u00.y);
            const float2 a10 = __half22float2(*(const __half2*)&u10.x);
            const float2 b10 = __half22float2(*(const __half2*)&u10.y);
            const float2 a01 = __half22float2(*(const __half2*)&u01.x);
            const float2 b01 = __half22float2(*(const __half2*)&u01.y);
            const float2 a11 = __half22float2(*(const __half2*)&u11.x);
            const float2 b11 = __half22float2(*(const __half2*)&u11.y);
            float2 s0, s1;
            s0.x = wv.x * a00.x + wv.y * a10.x + wv.z * a01.x + wv.w * a11.x;
            s0.y = wv.x * a00.y + wv.y * a10.y + wv.z * a01.y + wv.w * a11.y;
            s1.x = wv.x * b00.x + wv.y * b10.x + wv.z * b01.x + wv.w * b11.x;
            s1.y = wv.x * b00.y + wv.y * b10.y + wv.z * b01.y + wv.w * b11.y;
            const __half2 h0 = __float22half2_rn(s0);
            const __half2 h1 = __float22half2_rn(s1);
            const uint32_t off = (uint32_t)pp * 256 + bswz((uint32_t)pp, (uint32_t)lane * 8);
            *(uint2*)(smp + SM_A0 + off) =
                make_uint2(*(const uint32_t*)&h0, *(const uint32_t*)&h1);
        }
    }
    cp_wait0();
    __syncthreads();

    for (int t = 0; t < 9; ++t) {
        const int cur = t & 1;
        const uint32_t Acur = sb + (cur ? SM_A1 : SM_A0);
        const uint32_t Wcur = sb + (cur ? SM_W1 : SM_W0);
        char* const Anxt = smp + (cur ? SM_A0 : SM_A1);
        const uint32_t Wnxt = sb + (cur ? SM_W0 : SM_W1);

        if (t < 8) {
            stageW_async(Wnxt, g_Wf16 + (size_t)(t + 1) * 65536, tid);
            cp_commit();
            mma_tap_fused<true>(Acur, Wcur, acc,
                                g_tabI + (t + 1) * HW + p0,
                                g_tabW + (t + 1) * HW + p0,
                                xh2, Anxt,
                                a_row_in_warp, a_koff, b_n_in_pair, b_koff,
                                warp_m, warp_n, lane, warp);
            cp_wait0();
        } else {
            mma_tap_fused<false>(Acur, Wcur, acc, nullptr, nullptr,
                                 xh2, nullptr,
                                 a_row_in_warp, a_koff, b_n_in_pair, b_koff,
                                 warp_m, warp_n, lane, warp);
        }
        __syncthreads();
    }

    // ---- epilogue: acc -> Dsm[co][px] -> coalesced out ----
    float* Dsm = (float*)smp;
    {
        const int rbase = warp_m * 32 + (lane >> 2);
        const int cbase = warp_n * 64 + 2 * (lane & 3);
#pragma unroll
        for (int mi = 0; mi < 2; ++mi) {
#pragma unroll
            for (int ni = 0; ni < 8; ++ni) {
                const int rr = rbase + mi * 16;
                const int cc = cbase + ni * 8;
                Dsm[(cc    ) * 128 + rr    ] = acc[mi][ni][0];
                Dsm[(cc + 1) * 128 + rr    ] = acc[mi][ni][1];
                Dsm[(cc    ) * 128 + rr + 8] = acc[mi][ni][2];
                Dsm[(cc + 1) * 128 + rr + 8] = acc[mi][ni][3];
            }
        }
    }
    __syncthreads();

    {
        const float* bs = (const float*)(smp + SM_BIAS);
        float* ob = out + (size_t)b * COUT * HW + p0;
#pragma unroll 4
        for (int it = 0; it < 16; ++it) {
            const int co = it * 16 + warp;
            const float bv = bs[co];
            float4 v = ((const float4*)(Dsm + co * 128))[lane];
            v.x += bv; v.y += bv; v.z += bv; v.w += bv;
            ((float4*)(ob + (size_t)co * HW))[lane] = v;
        }
    }
}

// ---------------------------------------------------------------------------
extern "C" void kernel_launch(void* const* d_in, const int* in_sizes, int n_in,
                              void* d_out, int out_size) {
    const float* x      = (const float*)d_in[0];   // (4,128,128,256)
    const float* weight = (const float*)d_in[1];   // (256,128,3,3)
    const float* bias   = (const float*)d_in[2];   // (256,)
    const float* grid   = (const float*)d_in[3];   // (1,384,768,2)
    float* out = (float*)d_out;                    // (4,256,128,256)

    cudaFuncSetAttribute(sphere_hmma_kernel,
                         cudaFuncAttributeMaxDynamicSharedMemorySize, SM_TOTAL);

    {
        dim3 g(HW / 128, CIN / 32, B_);
        transpose_x_kernel<<<g, 256>>>(x);
    }
    prep_kernel<<<(9 * 32768 + 255) / 256, 256>>>(weight, grid);
    sphere_hmma_kernel<<<NTILES, NTHREADS, SM_TOTAL>>>(bias, out);
}

// round 14
// speedup vs baseline: 1.5417x; 1.5417x over previous
#include <cuda_runtime.h>
#include <cuda_fp16.h>
#include <cstdint>
#include <math.h>

// ---------------- problem constants ----------------
#define B_   4
#define CIN  128
#define COUT 256
#define H_   128
#define W_   256
#define HW   (H_ * W_)              // 32768
#define TILE_M 128                  // pixels per CTA
#define NTILES (B_ * HW / TILE_M)   // 1024
#define NTHREADS 512

// ---------------- device scratch ----------------
__device__ __half g_xh[(size_t)B_ * HW * CIN];       // 32 MB (B, HW, Cin) fp16
__device__ unsigned char g_Wf16[9 * 65536];          // per tap: 256 co x 256B (128 fp16), swizzled
__device__ int4   g_tabI[9 * HW];                    // gather indices (uint2 units into g_xh)
__device__ float4 g_tabW[9 * HW];                    // bilinear weights (edge-zeroed)

// ---------------- smem layout (1024-aligned base) ----------------
#define SM_A0   0            // 128 rows x 256B = 32KB
#define SM_A1   32768        // 32KB
#define SM_W0   65536        // 64KB
#define SM_W1   131072       // 64KB
#define SM_BIAS 196608       // 1KB
#define SM_TOTAL (197632 + 1024)
// epilogue reuses [0, 128KB) as Dsm[co][px] fp32

__device__ __forceinline__ uint32_t bswz(uint32_t row, uint32_t col) {
    return col ^ ((row & 7u) << 4);
}

__device__ __forceinline__ uint32_t smem_u32(const void* p) {
    uint32_t a;
    asm("{ .reg .u64 t; cvta.to.shared.u64 t, %1; cvt.u32.u64 %0, t; }" : "=r"(a) : "l"(p));
    return a;
}

__device__ __forceinline__ void ldm_x4(uint32_t& r0, uint32_t& r1, uint32_t& r2, uint32_t& r3,
                                       uint32_t addr) {
    asm volatile("ldmatrix.sync.aligned.m8n8.x4.shared.b16 {%0,%1,%2,%3}, [%4];"
                 : "=r"(r0), "=r"(r1), "=r"(r2), "=r"(r3) : "r"(addr));
}

__device__ __forceinline__ void mma_16816(float& c0, float& c1, float& c2, float& c3,
                                          uint32_t a0, uint32_t a1, uint32_t a2, uint32_t a3,
                                          uint32_t b0, uint32_t b1) {
    asm volatile(
        "mma.sync.aligned.m16n8k16.row.col.f32.f16.f16.f32 "
        "{%0,%1,%2,%3}, {%4,%5,%6,%7}, {%8,%9}, {%0,%1,%2,%3};"
        : "+f"(c0), "+f"(c1), "+f"(c2), "+f"(c3)
        : "r"(a0), "r"(a1), "r"(a2), "r"(a3), "r"(b0), "r"(b1));
}

__device__ __forceinline__ void cp_async16(uint32_t dst, const void* src) {
    asm volatile("cp.async.cg.shared.global [%0], [%1], 16;" :: "r"(dst), "l"(src) : "memory");
}
__device__ __forceinline__ void cp_commit() {
    asm volatile("cp.async.commit_group;" ::: "memory");
}
__device__ __forceinline__ void cp_wait0() {
    asm volatile("cp.async.wait_group 0;" ::: "memory");
}

// stage a 64KB pre-swizzled W block with 512 threads, non-blocking
__device__ __forceinline__ void stageW_async(uint32_t smem_dst, const unsigned char* src, int tid) {
#pragma unroll
    for (int i = 0; i < 8; ++i) {
        cp_async16(smem_dst + i * 8192 + tid * 16, src + i * 8192 + tid * 16);
    }
}

// ---------------------------------------------------------------------------
// Kernel 1 (fused prep): blockIdx.x < 16384 -> transpose tile (R8 layout);
// else -> weight + grid table prep. All blocks 256 threads.
// ---------------------------------------------------------------------------
#define NBLK_TRANS 16384            // (HW/32) * (CIN/32) * B_ = 1024*4*4
#define NBLK_PREP  1152             // 9*32768 / 256

__global__ void prep_all_kernel(const float* __restrict__ x,
                                const float* __restrict__ wsrc,
                                const float* __restrict__ gridp) {
    const int bid = blockIdx.x;
    if (bid < NBLK_TRANS) {
        // ---- transpose+convert x -> g_xh (R8-proven 32x32 tile, 32x8 thr) ----
        __shared__ float tile[32][33];
        const int b    = bid >> 12;                 // /4096
        const int cin0 = ((bid >> 10) & 3) * 32;    // 4 tiles of cin
        const int p0   = (bid & 1023) * 32;
        const int tx = threadIdx.x & 31;
        const int ty = threadIdx.x >> 5;            // 0..7
#pragma unroll
        for (int j = 0; j < 4; ++j)
            tile[ty + 8 * j][tx] =
                x[((size_t)b * CIN + (cin0 + ty + 8 * j)) * HW + (p0 + tx)];
        __syncthreads();
#pragma unroll
        for (int j = 0; j < 4; ++j)
            g_xh[((size_t)b * HW + (p0 + ty + 8 * j)) * CIN + (cin0 + tx)] =
                __float2half(tile[tx][ty + 8 * j]);
        return;
    }

    const int idx = (bid - NBLK_TRANS) * 256 + threadIdx.x;   // < 9*32768
    // ---- weight part: idx -> (t, co, cin) ----
    {
        const int cin = idx & 127;
        const int co  = (idx >> 7) & 255;
        const int t   = idx >> 15;
        const float v = wsrc[(co * CIN + cin) * 9 + t];
        const uint32_t off = (uint32_t)co * 256 + bswz(co, (uint32_t)cin * 2);
        *(__half*)(g_Wf16 + (size_t)t * 65536 + off) = __float2half(v);
    }
    // ---- grid part: idx -> (t, p) ----
    {
        const int p = idx & (HW - 1);
        const int t = idx >> 15;
        const int h = p >> 8;
        const int w = p & 255;
        const int r = t / 3;
        const int c = t - r * 3;

        const int gi = (h * 3 + r) * (W_ * 3) + (w * 3 + c);
        const float gx = gridp[2 * gi + 0];
        const float gy = gridp[2 * gi + 1];

        const float ix = ((gx + 1.0f) * (float)W_ - 1.0f) * 0.5f;
        const float iy = ((gy + 1.0f) * (float)H_ - 1.0f) * 0.5f;
        const float x0f = floorf(ix), y0f = floorf(iy);
        const float fx = ix - x0f, fy = iy - y0f;
        const int xx0 = (int)x0f, yy0 = (int)y0f;
        const int xx1 = xx0 + 1, yy1 = yy0 + 1;

        float w00 = (1.0f - fx) * (1.0f - fy);
        float w10 = fx * (1.0f - fy);
        float w01 = (1.0f - fx) * fy;
        float w11 = fx * fy;
        if (xx0 < 0 || xx0 >= W_) { w00 = 0.0f; w01 = 0.0f; }
        if (xx1 < 0 || xx1 >= W_) { w10 = 0.0f; w11 = 0.0f; }
        if (yy0 < 0 || yy0 >= H_) { w00 = 0.0f; w10 = 0.0f; }
        if (yy1 < 0 || yy1 >= H_) { w01 = 0.0f; w11 = 0.0f; }

        const int xi0 = min(max(xx0, 0), W_ - 1);
        const int xi1 = min(max(xx1, 0), W_ - 1);
        const int yi0 = min(max(yy0, 0), H_ - 1);
        const int yi1 = min(max(yy1, 0), H_ - 1);

        int4 e;
        e.x = (yi0 * W_ + xi0) * 32;
        e.y = (yi0 * W_ + xi1) * 32;
        e.z = (yi1 * W_ + xi0) * 32;
        e.w = (yi1 * W_ + xi1) * 32;
        g_tabI[idx] = e;
        g_tabW[idx] = make_float4(w00, w10, w01, w11);
    }
}

// ---------------------------------------------------------------------------
// fused tap (R8-proven): 8 k-steps; per k-step: gather LDGs for 1 px/warp,
// BATCHED B fragments (4 ldm in flight), A fragments, 16 MMAs, blend+STS.
// ---------------------------------------------------------------------------
template <bool GATHER>
__device__ __forceinline__ void mma_tap_fused(
    uint32_t Abase, uint32_t Wbase, float (*acc)[8][4],
    const int4* __restrict__ tI, const float4* __restrict__ tW,
    const uint2* __restrict__ xh2, char* __restrict__ Anxt,
    uint32_t a_row_in_warp, uint32_t a_koff,
    uint32_t b_n_in_pair, uint32_t b_koff,
    int warp_m, int warp_n, int lane, int warp) {

    int4 e;
    float4 wv;
    if (GATHER) {           // table entry for pixel of k-step 0
        e  = __ldg(tI + warp);
        wv = __ldg(tW + warp);
    }

#pragma unroll
    for (int k0 = 0; k0 < 8; ++k0) {
        // ---- issue gather LDGs for pixel (k0*16 + warp) ----
        uint2 u00, u10, u01, u11;
        if (GATHER) {
            u00 = __ldg(xh2 + e.x + lane);
            u10 = __ldg(xh2 + e.y + lane);
            u01 = __ldg(xh2 + e.z + lane);
            u11 = __ldg(xh2 + e.w + lane);
        }

        const uint32_t kb = (uint32_t)k0 * 32;

        // ---- B fragments (batched: all 4 ldm in flight) ----
        uint32_t bfr[8][2];
#pragma unroll
        for (int np = 0; np < 4; ++np) {
            const uint32_t n = (uint32_t)(warp_n * 64 + np * 16) + b_n_in_pair;
            const uint32_t addr = Wbase + n * 256 + bswz(n, kb + b_koff);
            ldm_x4(bfr[np * 2][0], bfr[np * 2][1],
                   bfr[np * 2 + 1][0], bfr[np * 2 + 1][1], addr);
        }

        // ---- A fragments ----
        uint32_t a0[2], a1[2], a2[2], a3[2];
#pragma unroll
        for (int mi = 0; mi < 2; ++mi) {
            const uint32_t row = (uint32_t)(warp_m * 32 + mi * 16) + a_row_in_warp;
            const uint32_t addr = Abase + row * 256 + bswz(row, kb + a_koff);
            ldm_x4(a0[mi], a1[mi], a2[mi], a3[mi], addr);
        }

        // ---- prefetch next table entry (consumed next k-step) ----
        int4 en;
        float4 wvn;
        if (GATHER && k0 < 7) {
            en  = __ldg(tI + (k0 + 1) * 16 + warp);
            wvn = __ldg(tW + (k0 + 1) * 16 + warp);
        }

        // ---- 16 MMAs ----
#pragma unroll
        for (int mi = 0; mi < 2; ++mi) {
#pragma unroll
            for (int ni = 0; ni < 8; ++ni) {
                mma_16816(acc[mi][ni][0], acc[mi][ni][1],
                          acc[mi][ni][2], acc[mi][ni][3],
                          a0[mi], a1[mi], a2[mi], a3[mi],
                          bfr[ni][0], bfr[ni][1]);
            }
        }

        // ---- blend + store gathered pixel ----
        if (GATHER) {
            const float2 a00 = __half22float2(*(const __half2*)&u00.x);
            const float2 b00 = __half22float2(*(const __half2*)&u00.y);
            const float2 a10 = __half22float2(*(const __half2*)&u10.x);
            const float2 b10 = __half22float2(*(const __half2*)&u10.y);
            const float2 a01 = __half22float2(*(const __half2*)&u01.x);
            const float2 b01 = __half22float2(*(const __half2*)&u01.y);
            const float2 a11 = __half22float2(*(const __half2*)&u11.x);
            const float2 b11 = __half22float2(*(const __half2*)&u11.y);

            float2 s0, s1;
            s0.x = wv.x * a00.x + wv.y * a10.x + wv.z * a01.x + wv.w * a11.x;
            s0.y = wv.x * a00.y + wv.y * a10.y + wv.z * a01.y + wv.w * a11.y;
            s1.x = wv.x * b00.x + wv.y * b10.x + wv.z * b01.x + wv.w * b11.x;
            s1.y = wv.x * b00.y + wv.y * b10.y + wv.z * b01.y + wv.w * b11.y;

            const __half2 h0 = __float22half2_rn(s0);
            const __half2 h1 = __float22half2_rn(s1);

            const int pp = k0 * 16 + warp;
            const uint32_t off = (uint32_t)pp * 256 + bswz((uint32_t)pp, (uint32_t)lane * 8);
            *(uint2*)(Anxt + off) =
                make_uint2(*(const uint32_t*)&h0, *(const uint32_t*)&h1);

            e = en;
            wv = wvn;
        }
    }
}

// ---------------------------------------------------------------------------
// Kernel 2: fused gather+mma, 512 threads / 16 warps, warp tile 32x64 (R8)
// ---------------------------------------------------------------------------
__global__ __launch_bounds__(NTHREADS, 1)
void sphere_hmma_kernel(const float* __restrict__ bias,
                        float* __restrict__ out) {
    extern __shared__ char dsm[];
    const uint32_t raw = smem_u32(dsm);
    const uint32_t sb  = (raw + 1023u) & ~1023u;
    char* const smp = dsm + (sb - raw);

    const int tid  = threadIdx.x;
    const int lane = tid & 31;
    const int warp = tid >> 5;          // 0..15
    const int warp_m = warp >> 2;       // 0..3
    const int warp_n = warp & 3;        // 0..3
    const int tile = blockIdx.x;
    const int b    = tile >> 8;
    const int p0   = (tile & 255) * TILE_M;

    if (tid < 256) ((float*)(smp + SM_BIAS))[tid] = bias[tid];

    const uint2* __restrict__ xh2 =
        (const uint2*)(g_xh + (size_t)b * HW * CIN);

    float acc[2][8][4];
#pragma unroll
    for (int mi = 0; mi < 2; ++mi)
#pragma unroll
        for (int ni = 0; ni < 8; ++ni)
#pragma unroll
            for (int q = 0; q < 4; ++q) acc[mi][ni][q] = 0.0f;

    const uint32_t a_row_in_warp = (uint32_t)(lane & 15);
    const uint32_t a_koff        = (uint32_t)((lane >> 4) << 4);
    const uint32_t b_n_in_pair   = (uint32_t)(((lane >> 4) & 1) * 8 + (lane & 7));
    const uint32_t b_koff        = (uint32_t)(((lane >> 3) & 1) << 4);

    // ---- prologue: stage W(0); gather A(0) (table-driven, unfused) ----
    stageW_async(sb + SM_W0, g_Wf16, tid);
    cp_commit();
    {
        const int4*   __restrict__ tI = g_tabI + p0;
        const float4* __restrict__ tW = g_tabW + p0;
#pragma unroll 2
        for (int i = 0; i < 8; ++i) {
            const int pp = i * 16 + warp;
            const int4   e  = __ldg(tI + pp);
            const float4 wv = __ldg(tW + pp);
            const uint2 u00 = __ldg(xh2 + e.x + lane);
            const uint2 u10 = __ldg(xh2 + e.y + lane);
            const uint2 u01 = __ldg(xh2 + e.z + lane);
            const uint2 u11 = __ldg(xh2 + e.w + lane);
            const float2 a00 = __half22float2(*(const __half2*)&u00.x);
            const float2 b00 = __half22float2(*(const __half2*)&u00.y);
            const float2 a10 = __half22float2(*(const __half2*)&u10.x);
            const float2 b10 = __half22float2(*(const __half2*)&u10.y);
            const float2 a01 = __half22float2(*(const __half2*)&u01.x);
            const float2 b01 = __half22float2(*(const __half2*)&u01.y);
            const float2 a11 = __half22float2(*(const __half2*)&u11.x);
            const float2 b11 = __half22float2(*(const __half2*)&u11.y);
            float2 s0, s1;
            s0.x = wv.x * a00.x + wv.y * a10.x + wv.z * a01.x + wv.w * a11.x;
            s0.y = wv.x * a00.y + wv.y * a10.y + wv.z * a01.y + wv.w * a11.y;
            s1.x = wv.x * b00.x + wv.y * b10.x + wv.z * b01.x + wv.w * b11.x;
            s1.y = wv.x * b00.y + wv.y * b10.y + wv.z * b01.y + wv.w * b11.y;
            const __half2 h0 = __float22half2_rn(s0);
            const __half2 h1 = __float22half2_rn(s1);
            const uint32_t off = (uint32_t)pp * 256 + bswz((uint32_t)pp, (uint32_t)lane * 8);
            *(uint2*)(smp + SM_A0 + off) =
                make_uint2(*(const uint32_t*)&h0, *(const uint32_t*)&h1);
        }
    }
    cp_wait0();
    __syncthreads();

    for (int t = 0; t < 9; ++t) {
        const int cur = t & 1;
        const uint32_t Acur = sb + (cur ? SM_A1 : SM_A0);
        const uint32_t Wcur = sb + (cur ? SM_W1 : SM_W0);
        char* const Anxt = smp + (cur ? SM_A0 : SM_A1);
        const uint32_t Wnxt = sb + (cur ? SM_W0 : SM_W1);

        if (t < 8) {
            stageW_async(Wnxt, g_Wf16 + (size_t)(t + 1) * 65536, tid);
            cp_commit();
            mma_tap_fused<true>(Acur, Wcur, acc,
                                g_tabI + (t + 1) * HW + p0,
                                g_tabW + (t + 1) * HW + p0,
                                xh2, Anxt,
                                a_row_in_warp, a_koff, b_n_in_pair, b_koff,
                                warp_m, warp_n, lane, warp);
            cp_wait0();
        } else {
            mma_tap_fused<false>(Acur, Wcur, acc, nullptr, nullptr,
                                 xh2, nullptr,
                                 a_row_in_warp, a_koff, b_n_in_pair, b_koff,
                                 warp_m, warp_n, lane, warp);
        }
        __syncthreads();
    }

    // ---- epilogue: acc -> Dsm[co][px] -> coalesced out ----
    float* Dsm = (float*)smp;
    {
        const int rbase = warp_m * 32 + (lane >> 2);
        const int cbase = warp_n * 64 + 2 * (lane & 3);
#pragma unroll
        for (int mi = 0; mi < 2; ++mi) {
#pragma unroll
            for (int ni = 0; ni < 8; ++ni) {
                const int rr = rbase + mi * 16;
                const int cc = cbase + ni * 8;
                Dsm[(cc    ) * 128 + rr    ] = acc[mi][ni][0];
                Dsm[(cc + 1) * 128 + rr    ] = acc[mi][ni][1];
                Dsm[(cc    ) * 128 + rr + 8] = acc[mi][ni][2];
                Dsm[(cc + 1) * 128 + rr + 8] = acc[mi][ni][3];
            }
        }
    }
    __syncthreads();

    {
        const float* bs = (const float*)(smp + SM_BIAS);
        float* ob = out + (size_t)b * COUT * HW + p0;
#pragma unroll 4
        for (int it = 0; it < 16; ++it) {
            const int co = it * 16 + warp;
            const float bv = bs[co];
            float4 v = ((const float4*)(Dsm + co * 128))[lane];
            v.x += bv; v.y += bv; v.z += bv; v.w += bv;
            ((float4*)(ob + (size_t)co * HW))[lane] = v;
        }
    }
}

// ---------------------------------------------------------------------------
extern "C" void kernel_launch(void* const* d_in, const int* in_sizes, int n_in,
                              void* d_out, int out_size) {
    const float* x      = (const float*)d_in[0];   // (4,128,128,256)
    const float* weight = (const float*)d_in[1];   // (256,128,3,3)
    const float* bias   = (const float*)d_in[2];   // (256,)
    const float* grid   = (const float*)d_in[3];   // (1,384,768,2)
    float* out = (float*)d_out;                    // (4,256,128,256)

    cudaFuncSetAttribute(sphere_hmma_kernel,
                         cudaFuncAttributeMaxDynamicSharedMemorySize, SM_TOTAL);

    prep_all_kernel<<<NBLK_TRANS + NBLK_PREP, 256>>>(x, weight, grid);
    sphere_hmma_kernel<<<NTILES, NTHREADS, SM_TOTAL>>>(bias, out);
}

// round 15
// speedup vs baseline: 1.6764x; 1.0874x over previous
#include <cuda_runtime.h>
#include <cuda_fp16.h>
#include <cstdint>
#include <math.h>

// ---------------- problem constants ----------------
#define B_   4
#define CIN  128
#define COUT 256
#define H_   128
#define W_   256
#define HW   (H_ * W_)              // 32768
#define TILE_M 128                  // pixels per CTA
#define NTILES (B_ * HW / TILE_M)   // 1024
#define NTHREADS 512

// ---------------- device scratch ----------------
__device__ __half g_xh[(size_t)B_ * HW * CIN];       // 32 MB (B, HW, Cin) fp16
__device__ unsigned char g_Wf16[9 * 65536];          // per tap: 256 co x 256B (128 fp16), swizzled
__device__ int4   g_tabI[9 * HW];                    // gather indices (uint2 units into g_xh)
__device__ float4 g_tabW[9 * HW];                    // bilinear weights (edge-zeroed)

// ---------------- smem layout (1024-aligned base) ----------------
#define SM_A0   0            // 128 rows x 256B = 32KB
#define SM_A1   32768        // 32KB
#define SM_W0   65536        // 64KB
#define SM_W1   131072       // 64KB
#define SM_BIAS 196608       // 1KB
#define SM_TOTAL (197632 + 1024)
// epilogue reuses [0, ~135KB) as Dsm[co][132] fp32 (padded stride, conflict-free)
#define DSM_STRIDE 132

__device__ __forceinline__ uint32_t bswz(uint32_t row, uint32_t col) {
    return col ^ ((row & 7u) << 4);
}

__device__ __forceinline__ uint32_t smem_u32(const void* p) {
    uint32_t a;
    asm("{ .reg .u64 t; cvta.to.shared.u64 t, %1; cvt.u32.u64 %0, t; }" : "=r"(a) : "l"(p));
    return a;
}

__device__ __forceinline__ void ldm_x4(uint32_t& r0, uint32_t& r1, uint32_t& r2, uint32_t& r3,
                                       uint32_t addr) {
    asm volatile("ldmatrix.sync.aligned.m8n8.x4.shared.b16 {%0,%1,%2,%3}, [%4];"
                 : "=r"(r0), "=r"(r1), "=r"(r2), "=r"(r3) : "r"(addr));
}

__device__ __forceinline__ void mma_16816(float& c0, float& c1, float& c2, float& c3,
                                          uint32_t a0, uint32_t a1, uint32_t a2, uint32_t a3,
                                          uint32_t b0, uint32_t b1) {
    asm volatile(
        "mma.sync.aligned.m16n8k16.row.col.f32.f16.f16.f32 "
        "{%0,%1,%2,%3}, {%4,%5,%6,%7}, {%8,%9}, {%0,%1,%2,%3};"
        : "+f"(c0), "+f"(c1), "+f"(c2), "+f"(c3)
        : "r"(a0), "r"(a1), "r"(a2), "r"(a3), "r"(b0), "r"(b1));
}

__device__ __forceinline__ void cp_async16(uint32_t dst, const void* src) {
    asm volatile("cp.async.cg.shared.global [%0], [%1], 16;" :: "r"(dst), "l"(src) : "memory");
}
__device__ __forceinline__ void cp_commit() {
    asm volatile("cp.async.commit_group;" ::: "memory");
}
__device__ __forceinline__ void cp_wait0() {
    asm volatile("cp.async.wait_group 0;" ::: "memory");
}

// stage a 64KB pre-swizzled W block with 512 threads, non-blocking
__device__ __forceinline__ void stageW_async(uint32_t smem_dst, const unsigned char* src, int tid) {
#pragma unroll
    for (int i = 0; i < 8; ++i) {
        cp_async16(smem_dst + i * 8192 + tid * 16, src + i * 8192 + tid * 16);
    }
}

// ---------------------------------------------------------------------------
// half2 bilinear blend: 4 corners (2 half2 each) x broadcast weights -> STS
// ---------------------------------------------------------------------------
__device__ __forceinline__ void blend_store_h2(char* __restrict__ abuf,
                                               const uint2 u00, const uint2 u10,
                                               const uint2 u01, const uint2 u11,
                                               const float4 wv, int pp, int lane) {
    const __half2 w00 = __float2half2_rn(wv.x);
    const __half2 w10 = __float2half2_rn(wv.y);
    const __half2 w01 = __float2half2_rn(wv.z);
    const __half2 w11 = __float2half2_rn(wv.w);

    __half2 s0 = __hmul2(w00, *(const __half2*)&u00.x);
    __half2 s1 = __hmul2(w00, *(const __half2*)&u00.y);
    s0 = __hfma2(w10, *(const __half2*)&u10.x, s0);
    s1 = __hfma2(w10, *(const __half2*)&u10.y, s1);
    s0 = __hfma2(w01, *(const __half2*)&u01.x, s0);
    s1 = __hfma2(w01, *(const __half2*)&u01.y, s1);
    s0 = __hfma2(w11, *(const __half2*)&u11.x, s0);
    s1 = __hfma2(w11, *(const __half2*)&u11.y, s1);

    const uint32_t off = (uint32_t)pp * 256 + bswz((uint32_t)pp, (uint32_t)lane * 8);
    *(uint2*)(abuf + off) = make_uint2(*(const uint32_t*)&s0, *(const uint32_t*)&s1);
}

// ---------------------------------------------------------------------------
// Kernel 1 (fused prep): blockIdx.x < 16384 -> transpose tile;
// else -> weight + grid table prep. All blocks 256 threads.
// ---------------------------------------------------------------------------
#define NBLK_TRANS 16384            // (HW/32) * (CIN/32) * B_
#define NBLK_PREP  1152             // 9*32768 / 256

__global__ void prep_all_kernel(const float* __restrict__ x,
                                const float* __restrict__ wsrc,
                                const float* __restrict__ gridp) {
    const int bid = blockIdx.x;
    if (bid < NBLK_TRANS) {
        __shared__ float tile[32][33];
        const int b    = bid >> 12;
        const int cin0 = ((bid >> 10) & 3) * 32;
        const int p0   = (bid & 1023) * 32;
        const int tx = threadIdx.x & 31;
        const int ty = threadIdx.x >> 5;
#pragma unroll
        for (int j = 0; j < 4; ++j)
            tile[ty + 8 * j][tx] =
                x[((size_t)b * CIN + (cin0 + ty + 8 * j)) * HW + (p0 + tx)];
        __syncthreads();
#pragma unroll
        for (int j = 0; j < 4; ++j)
            g_xh[((size_t)b * HW + (p0 + ty + 8 * j)) * CIN + (cin0 + tx)] =
                __float2half(tile[tx][ty + 8 * j]);
        return;
    }

    const int idx = (bid - NBLK_TRANS) * 256 + threadIdx.x;   // < 9*32768
    {
        const int cin = idx & 127;
        const int co  = (idx >> 7) & 255;
        const int t   = idx >> 15;
        const float v = wsrc[(co * CIN + cin) * 9 + t];
        const uint32_t off = (uint32_t)co * 256 + bswz(co, (uint32_t)cin * 2);
        *(__half*)(g_Wf16 + (size_t)t * 65536 + off) = __float2half(v);
    }
    {
        const int p = idx & (HW - 1);
        const int t = idx >> 15;
        const int h = p >> 8;
        const int w = p & 255;
        const int r = t / 3;
        const int c = t - r * 3;

        const int gi = (h * 3 + r) * (W_ * 3) + (w * 3 + c);
        const float gx = gridp[2 * gi + 0];
        const float gy = gridp[2 * gi + 1];

        const float ix = ((gx + 1.0f) * (float)W_ - 1.0f) * 0.5f;
        const float iy = ((gy + 1.0f) * (float)H_ - 1.0f) * 0.5f;
        const float x0f = floorf(ix), y0f = floorf(iy);
        const float fx = ix - x0f, fy = iy - y0f;
        const int xx0 = (int)x0f, yy0 = (int)y0f;
        const int xx1 = xx0 + 1, yy1 = yy0 + 1;

        float w00 = (1.0f - fx) * (1.0f - fy);
        float w10 = fx * (1.0f - fy);
        float w01 = (1.0f - fx) * fy;
        float w11 = fx * fy;
        if (xx0 < 0 || xx0 >= W_) { w00 = 0.0f; w01 = 0.0f; }
        if (xx1 < 0 || xx1 >= W_) { w10 = 0.0f; w11 = 0.0f; }
        if (yy0 < 0 || yy0 >= H_) { w00 = 0.0f; w10 = 0.0f; }
        if (yy1 < 0 || yy1 >= H_) { w01 = 0.0f; w11 = 0.0f; }

        const int xi0 = min(max(xx0, 0), W_ - 1);
        const int xi1 = min(max(xx1, 0), W_ - 1);
        const int yi0 = min(max(yy0, 0), H_ - 1);
        const int yi1 = min(max(yy1, 0), H_ - 1);

        int4 e;
        e.x = (yi0 * W_ + xi0) * 32;
        e.y = (yi0 * W_ + xi1) * 32;
        e.z = (yi1 * W_ + xi0) * 32;
        e.w = (yi1 * W_ + xi1) * 32;
        g_tabI[idx] = e;
        g_tabW[idx] = make_float4(w00, w10, w01, w11);
    }
}

// ---------------------------------------------------------------------------
// fused tap (R8-proven): 8 k-steps; per k-step: gather LDGs for 1 px/warp,
// BATCHED B fragments (4 ldm in flight), A fragments, 16 MMAs, h2 blend+STS.
// ---------------------------------------------------------------------------
template <bool GATHER>
__device__ __forceinline__ void mma_tap_fused(
    uint32_t Abase, uint32_t Wbase, float (*acc)[8][4],
    const int4* __restrict__ tI, const float4* __restrict__ tW,
    const uint2* __restrict__ xh2, char* __restrict__ Anxt,
    uint32_t a_row_in_warp, uint32_t a_koff,
    uint32_t b_n_in_pair, uint32_t b_koff,
    int warp_m, int warp_n, int lane, int warp) {

    int4 e;
    float4 wv;
    if (GATHER) {           // table entry for pixel of k-step 0
        e  = __ldg(tI + warp);
        wv = __ldg(tW + warp);
    }

#pragma unroll
    for (int k0 = 0; k0 < 8; ++k0) {
        // ---- issue gather LDGs for pixel (k0*16 + warp) ----
        uint2 u00, u10, u01, u11;
        if (GATHER) {
            u00 = __ldg(xh2 + e.x + lane);
            u10 = __ldg(xh2 + e.y + lane);
            u01 = __ldg(xh2 + e.z + lane);
            u11 = __ldg(xh2 + e.w + lane);
        }

        const uint32_t kb = (uint32_t)k0 * 32;

        // ---- B fragments (batched: all 4 ldm in flight) ----
        uint32_t bfr[8][2];
#pragma unroll
        for (int np = 0; np < 4; ++np) {
            const uint32_t n = (uint32_t)(warp_n * 64 + np * 16) + b_n_in_pair;
            const uint32_t addr = Wbase + n * 256 + bswz(n, kb + b_koff);
            ldm_x4(bfr[np * 2][0], bfr[np * 2][1],
                   bfr[np * 2 + 1][0], bfr[np * 2 + 1][1], addr);
        }

        // ---- A fragments ----
        uint32_t a0[2], a1[2], a2[2], a3[2];
#pragma unroll
        for (int mi = 0; mi < 2; ++mi) {
            const uint32_t row = (uint32_t)(warp_m * 32 + mi * 16) + a_row_in_warp;
            const uint32_t addr = Abase + row * 256 + bswz(row, kb + a_koff);
            ldm_x4(a0[mi], a1[mi], a2[mi], a3[mi], addr);
        }

        // ---- prefetch next table entry (consumed next k-step) ----
        int4 en;
        float4 wvn;
        if (GATHER && k0 < 7) {
            en  = __ldg(tI + (k0 + 1) * 16 + warp);
            wvn = __ldg(tW + (k0 + 1) * 16 + warp);
        }

        // ---- 16 MMAs ----
#pragma unroll
        for (int mi = 0; mi < 2; ++mi) {
#pragma unroll
            for (int ni = 0; ni < 8; ++ni) {
                mma_16816(acc[mi][ni][0], acc[mi][ni][1],
                          acc[mi][ni][2], acc[mi][ni][3],
                          a0[mi], a1[mi], a2[mi], a3[mi],
                          bfr[ni][0], bfr[ni][1]);
            }
        }

        // ---- blend (half2) + store gathered pixel ----
        if (GATHER) {
            blend_store_h2(Anxt, u00, u10, u01, u11, wv, k0 * 16 + warp, lane);
            e = en;
            wv = wvn;
        }
    }
}

// ---------------------------------------------------------------------------
// Kernel 2: fused gather+mma, 512 threads / 16 warps, warp tile 32x64 (R8)
// ---------------------------------------------------------------------------
__global__ __launch_bounds__(NTHREADS, 1)
void sphere_hmma_kernel(const float* __restrict__ bias,
                        float* __restrict__ out) {
    extern __shared__ char dsm[];
    const uint32_t raw = smem_u32(dsm);
    const uint32_t sb  = (raw + 1023u) & ~1023u;
    char* const smp = dsm + (sb - raw);

    const int tid  = threadIdx.x;
    const int lane = tid & 31;
    const int warp = tid >> 5;          // 0..15
    const int warp_m = warp >> 2;       // 0..3
    const int warp_n = warp & 3;        // 0..3
    const int tile = blockIdx.x;
    const int b    = tile >> 8;
    const int p0   = (tile & 255) * TILE_M;

    if (tid < 256) ((float*)(smp + SM_BIAS))[tid] = bias[tid];

    const uint2* __restrict__ xh2 =
        (const uint2*)(g_xh + (size_t)b * HW * CIN);

    float acc[2][8][4];
#pragma unroll
    for (int mi = 0; mi < 2; ++mi)
#pragma unroll
        for (int ni = 0; ni < 8; ++ni)
#pragma unroll
            for (int q = 0; q < 4; ++q) acc[mi][ni][q] = 0.0f;

    const uint32_t a_row_in_warp = (uint32_t)(lane & 15);
    const uint32_t a_koff        = (uint32_t)((lane >> 4) << 4);
    const uint32_t b_n_in_pair   = (uint32_t)(((lane >> 4) & 1) * 8 + (lane & 7));
    const uint32_t b_koff        = (uint32_t)(((lane >> 3) & 1) << 4);

    // ---- prologue: stage W(0); gather A(0) (table-driven, unfused) ----
    stageW_async(sb + SM_W0, g_Wf16, tid);
    cp_commit();
    {
        const int4*   __restrict__ tI = g_tabI + p0;
        const float4* __restrict__ tW = g_tabW + p0;
#pragma unroll 2
        for (int i = 0; i < 8; ++i) {
            const int pp = i * 16 + warp;
            const int4   e  = __ldg(tI + pp);
            const float4 wv = __ldg(tW + pp);
            const uint2 u00 = __ldg(xh2 + e.x + lane);
            const uint2 u10 = __ldg(xh2 + e.y + lane);
            const uint2 u01 = __ldg(xh2 + e.z + lane);
            const uint2 u11 = __ldg(xh2 + e.w + lane);
            blend_store_h2(smp + SM_A0, u00, u10, u01, u11, wv, pp, lane);
        }
    }
    cp_wait0();
    __syncthreads();

    for (int t = 0; t < 9; ++t) {
        const int cur = t & 1;
        const uint32_t Acur = sb + (cur ? SM_A1 : SM_A0);
        const uint32_t Wcur = sb + (cur ? SM_W1 : SM_W0);
        char* const Anxt = smp + (cur ? SM_A0 : SM_A1);
        const uint32_t Wnxt = sb + (cur ? SM_W0 : SM_W1);

        if (t < 8) {
            stageW_async(Wnxt, g_Wf16 + (size_t)(t + 1) * 65536, tid);
            cp_commit();
            mma_tap_fused<true>(Acur, Wcur, acc,
                                g_tabI + (t + 1) * HW + p0,
                                g_tabW + (t + 1) * HW + p0,
                                xh2, Anxt,
                                a_row_in_warp, a_koff, b_n_in_pair, b_koff,
                                warp_m, warp_n, lane, warp);
            cp_wait0();
        } else {
            mma_tap_fused<false>(Acur, Wcur, acc, nullptr, nullptr,
                                 xh2, nullptr,
                                 a_row_in_warp, a_koff, b_n_in_pair, b_koff,
                                 warp_m, warp_n, lane, warp);
        }
        __syncthreads();
    }

    // ---- epilogue: acc -> Dsm[co][px] (padded stride) -> coalesced out ----
    float* Dsm = (float*)smp;   // 256 x DSM_STRIDE fp32, conflict-free
    {
        const int rbase = warp_m * 32 + (lane >> 2);
        const int cbase = warp_n * 64 + 2 * (lane & 3);
#pragma unroll
        for (int mi = 0; mi < 2; ++mi) {
#pragma unroll
            for (int ni = 0; ni < 8; ++ni) {
                const int rr = rbase + mi * 16;
                const int cc = cbase + ni * 8;
                Dsm[(cc    ) * DSM_STRIDE + rr    ] = acc[mi][ni][0];
                Dsm[(cc + 1) * DSM_STRIDE + rr    ] = acc[mi][ni][1];
                Dsm[(cc    ) * DSM_STRIDE + rr + 8] = acc[mi][ni][2];
                Dsm[(cc + 1) * DSM_STRIDE + rr + 8] = acc[mi][ni][3];
            }
        }
    }
    __syncthreads();

    {
        const float* bs = (const float*)(smp + SM_BIAS);
        float* ob = out + (size_t)b * COUT * HW + p0;
#pragma unroll 4
        for (int it = 0; it < 16; ++it) {
            const int co = it * 16 + warp;
            const float bv = bs[co];
            float4 v = ((const float4*)(Dsm + co * DSM_STRIDE))[lane];
            v.x += bv; v.y += bv; v.z += bv; v.w += bv;
            ((float4*)(ob + (size_t)co * HW))[lane] = v;
        }
    }
}

// ---------------------------------------------------------------------------
extern "C" void kernel_launch(void* const* d_in, const int* in_sizes, int n_in,
                              void* d_out, int out_size) {
    const float* x      = (const float*)d_in[0];   // (4,128,128,256)
    const float* weight = (const float*)d_in[1];   // (256,128,3,3)
    const float* bias   = (const float*)d_in[2];   // (256,)
    const float* grid   = (const float*)d_in[3];   // (1,384,768,2)
    float* out = (float*)d_out;                    // (4,256,128,256)

    cudaFuncSetAttribute(sphere_hmma_kernel,
                         cudaFuncAttributeMaxDynamicSharedMemorySize, SM_TOTAL);

    prep_all_kernel<<<NBLK_TRANS + NBLK_PREP, 256>>>(x, weight, grid);
    sphere_hmma_kernel<<<NTILES, NTHREADS, SM_TOTAL>>>(bias, out);
}

// round 17
// speedup vs baseline: 1.7083x; 1.0190x over previous
#include <cuda_runtime.h>
#include <cuda_fp16.h>
#include <cstdint>
#include <math.h>

// ---------------- problem constants ----------------
#define B_   4
#define CIN  128
#define COUT 256
#define H_   128
#define W_   256
#define HW   (H_ * W_)              // 32768
#define TILE_M 128                  // pixels per CTA
#define NTILES (B_ * HW / TILE_M)   // 1024
#define NTHREADS 512

// ---------------- device scratch ----------------
__device__ __half g_xh[(size_t)B_ * HW * CIN];       // 32 MB (B, HW, Cin) fp16
__device__ unsigned char g_Wf16[9 * 65536];          // per tap: 256 co x 256B (128 fp16), swizzled
// packed gather table: .x = p00|p10<<16, .y = p01|p11<<16 (pixel ids),
//                      .z = half2(w00,w10), .w = half2(w01,w11)
__device__ uint4 g_tab[9 * HW];                      // 4.7 MB

// ---------------- smem layout (1024-aligned base) ----------------
#define SM_A0   0            // 128 rows x 256B = 32KB
#define SM_A1   32768        // 32KB
#define SM_W0   65536        // 64KB
#define SM_W1   131072       // 64KB
#define SM_BIAS 196608       // 1KB
#define SM_TOTAL (197632 + 1024)
// epilogue reuses [0, ~135KB) as Dsm[co][132] fp32 (padded stride, conflict-free)
#define DSM_STRIDE 132

__device__ __forceinline__ uint32_t bswz(uint32_t row, uint32_t col) {
    return col ^ ((row & 7u) << 4);
}

__device__ __forceinline__ uint32_t smem_u32(const void* p) {
    uint32_t a;
    asm("{ .reg .u64 t; cvta.to.shared.u64 t, %1; cvt.u32.u64 %0, t; }" : "=r"(a) : "l"(p));
    return a;
}

__device__ __forceinline__ void ldm_x4(uint32_t& r0, uint32_t& r1, uint32_t& r2, uint32_t& r3,
                                       uint32_t addr) {
    asm volatile("ldmatrix.sync.aligned.m8n8.x4.shared.b16 {%0,%1,%2,%3}, [%4];"
                 : "=r"(r0), "=r"(r1), "=r"(r2), "=r"(r3) : "r"(addr));
}

__device__ __forceinline__ void mma_16816(float& c0, float& c1, float& c2, float& c3,
                                          uint32_t a0, uint32_t a1, uint32_t a2, uint32_t a3,
                                          uint32_t b0, uint32_t b1) {
    asm volatile(
        "mma.sync.aligned.m16n8k16.row.col.f32.f16.f16.f32 "
        "{%0,%1,%2,%3}, {%4,%5,%6,%7}, {%8,%9}, {%0,%1,%2,%3};"
        : "+f"(c0), "+f"(c1), "+f"(c2), "+f"(c3)
        : "r"(a0), "r"(a1), "r"(a2), "r"(a3), "r"(b0), "r"(b1));
}

__device__ __forceinline__ void cp_async16(uint32_t dst, const void* src) {
    asm volatile("cp.async.cg.shared.global [%0], [%1], 16;" :: "r"(dst), "l"(src) : "memory");
}
__device__ __forceinline__ void cp_commit() {
    asm volatile("cp.async.commit_group;" ::: "memory");
}
__device__ __forceinline__ void cp_wait0() {
    asm volatile("cp.async.wait_group 0;" ::: "memory");
}

// stage a 64KB pre-swizzled W block with 512 threads, non-blocking
__device__ __forceinline__ void stageW_async(uint32_t smem_dst, const unsigned char* src, int tid) {
#pragma unroll
    for (int i = 0; i < 8; ++i) {
        cp_async16(smem_dst + i * 8192 + tid * 16, src + i * 8192 + tid * 16);
    }
}

// ---------------------------------------------------------------------------
// half2 bilinear blend from packed weights: 4 corners x broadcast half2 -> STS
// ---------------------------------------------------------------------------
__device__ __forceinline__ void blend_store_h2(char* __restrict__ abuf,
                                               const uint2 u00, const uint2 u10,
                                               const uint2 u01, const uint2 u11,
                                               const uint32_t wz, const uint32_t ww,
                                               int pp, int lane) {
    const __half2 wp01 = *(const __half2*)&wz;   // (w00, w10)
    const __half2 wp23 = *(const __half2*)&ww;   // (w01, w11)
    const __half2 w00 = __half2half2(__low2half(wp01));
    const __half2 w10 = __half2half2(__high2half(wp01));
    const __half2 w01 = __half2half2(__low2half(wp23));
    const __half2 w11 = __half2half2(__high2half(wp23));

    __half2 s0 = __hmul2(w00, *(const __half2*)&u00.x);
    __half2 s1 = __hmul2(w00, *(const __half2*)&u00.y);
    s0 = __hfma2(w10, *(const __half2*)&u10.x, s0);
    s1 = __hfma2(w10, *(const __half2*)&u10.y, s1);
    s0 = __hfma2(w01, *(const __half2*)&u01.x, s0);
    s1 = __hfma2(w01, *(const __half2*)&u01.y, s1);
    s0 = __hfma2(w11, *(const __half2*)&u11.x, s0);
    s1 = __hfma2(w11, *(const __half2*)&u11.y, s1);

    const uint32_t off = (uint32_t)pp * 256 + bswz((uint32_t)pp, (uint32_t)lane * 8);
    *(uint2*)(abuf + off) = make_uint2(*(const uint32_t*)&s0, *(const uint32_t*)&s1);
}

// ---------------------------------------------------------------------------
// Kernel 1 (fused prep): blockIdx.x < 16384 -> transpose tile;
// else -> weight + packed grid table prep. All blocks 256 threads.
// ---------------------------------------------------------------------------
#define NBLK_TRANS 16384            // (HW/32) * (CIN/32) * B_
#define NBLK_PREP  1152             // 9*32768 / 256

__global__ void prep_all_kernel(const float* __restrict__ x,
                                const float* __restrict__ wsrc,
                                const float* __restrict__ gridp) {
    const int bid = blockIdx.x;
    if (bid < NBLK_TRANS) {
        __shared__ float tile[32][33];
        const int b    = bid >> 12;
        const int cin0 = ((bid >> 10) & 3) * 32;
        const int p0   = (bid & 1023) * 32;
        const int tx = threadIdx.x & 31;
        const int ty = threadIdx.x >> 5;
#pragma unroll
        for (int j = 0; j < 4; ++j)
            tile[ty + 8 * j][tx] =
                x[((size_t)b * CIN + (cin0 + ty + 8 * j)) * HW + (p0 + tx)];
        __syncthreads();
#pragma unroll
        for (int j = 0; j < 4; ++j)
            g_xh[((size_t)b * HW + (p0 + ty + 8 * j)) * CIN + (cin0 + tx)] =
                __float2half(tile[tx][ty + 8 * j]);
        return;
    }

    const int idx = (bid - NBLK_TRANS) * 256 + threadIdx.x;   // < 9*32768
    {
        const int cin = idx & 127;
        const int co  = (idx >> 7) & 255;
        const int t   = idx >> 15;
        const float v = wsrc[(co * CIN + cin) * 9 + t];
        const uint32_t off = (uint32_t)co * 256 + bswz(co, (uint32_t)cin * 2);
        *(__half*)(g_Wf16 + (size_t)t * 65536 + off) = __float2half(v);
    }
    {
        const int p = idx & (HW - 1);
        const int t = idx >> 15;
        const int h = p >> 8;
        const int w = p & 255;
        const int r = t / 3;
        const int c = t - r * 3;

        const int gi = (h * 3 + r) * (W_ * 3) + (w * 3 + c);
        const float gx = gridp[2 * gi + 0];
        const float gy = gridp[2 * gi + 1];

        const float ix = ((gx + 1.0f) * (float)W_ - 1.0f) * 0.5f;
        const float iy = ((gy + 1.0f) * (float)H_ - 1.0f) * 0.5f;
        const float x0f = floorf(ix), y0f = floorf(iy);
        const float fx = ix - x0f, fy = iy - y0f;
        const int xx0 = (int)x0f, yy0 = (int)y0f;
        const int xx1 = xx0 + 1, yy1 = yy0 + 1;

        float w00 = (1.0f - fx) * (1.0f - fy);
        float w10 = fx * (1.0f - fy);
        float w01 = (1.0f - fx) * fy;
        float w11 = fx * fy;
        if (xx0 < 0 || xx0 >= W_) { w00 = 0.0f; w01 = 0.0f; }
        if (xx1 < 0 || xx1 >= W_) { w10 = 0.0f; w11 = 0.0f; }
        if (yy0 < 0 || yy0 >= H_) { w00 = 0.0f; w10 = 0.0f; }
        if (yy1 < 0 || yy1 >= H_) { w01 = 0.0f; w11 = 0.0f; }

        const int xi0 = min(max(xx0, 0), W_ - 1);
        const int xi1 = min(max(xx1, 0), W_ - 1);
        const int yi0 = min(max(yy0, 0), H_ - 1);
        const int yi1 = min(max(yy1, 0), H_ - 1);

        const uint32_t p00 = (uint32_t)(yi0 * W_ + xi0);
        const uint32_t p10 = (uint32_t)(yi0 * W_ + xi1);
        const uint32_t p01 = (uint32_t)(yi1 * W_ + xi0);
        const uint32_t p11 = (uint32_t)(yi1 * W_ + xi1);

        const __half2 wz = __floats2half2_rn(w00, w10);
        const __half2 ww = __floats2half2_rn(w01, w11);

        uint4 q;
        q.x = p00 | (p10 << 16);
        q.y = p01 | (p11 << 16);
        q.z = *(const uint32_t*)&wz;
        q.w = *(const uint32_t*)&ww;
        g_tab[idx] = q;
    }
}

// ---------------------------------------------------------------------------
// fused tap (R8-proven): 8 k-steps; per k-step: gather LDGs for 1 px/warp,
// BATCHED B fragments (4 ldm in flight), A fragments, 16 MMAs, h2 blend+STS.
// ---------------------------------------------------------------------------
template <bool GATHER>
__device__ __forceinline__ void mma_tap_fused(
    uint32_t Abase, uint32_t Wbase, float (*acc)[8][4],
    const uint4* __restrict__ tab,
    const uint2* __restrict__ xh2, char* __restrict__ Anxt,
    uint32_t a_row_in_warp, uint32_t a_koff,
    uint32_t b_n_in_pair, uint32_t b_koff,
    int warp_m, int warp_n, int lane, int warp) {

    uint4 q;
    if (GATHER) {           // table entry for pixel of k-step 0
        q = __ldg(tab + warp);
    }

#pragma unroll
    for (int k0 = 0; k0 < 8; ++k0) {
        // ---- issue gather LDGs for pixel (k0*16 + warp) ----
        uint2 u00, u10, u01, u11;
        if (GATHER) {
            u00 = __ldg(xh2 + (q.x & 0xFFFFu) * 32 + lane);
            u10 = __ldg(xh2 + (q.x >> 16) * 32 + lane);
            u01 = __ldg(xh2 + (q.y & 0xFFFFu) * 32 + lane);
            u11 = __ldg(xh2 + (q.y >> 16) * 32 + lane);
        }

        const uint32_t kb = (uint32_t)k0 * 32;

        // ---- B fragments (batched: all 4 ldm in flight) ----
        uint32_t bfr[8][2];
#pragma unroll
        for (int np = 0; np < 4; ++np) {
            const uint32_t n = (uint32_t)(warp_n * 64 + np * 16) + b_n_in_pair;
            const uint32_t addr = Wbase + n * 256 + bswz(n, kb + b_koff);
            ldm_x4(bfr[np * 2][0], bfr[np * 2][1],
                   bfr[np * 2 + 1][0], bfr[np * 2 + 1][1], addr);
        }

        // ---- A fragments ----
        uint32_t a0[2], a1[2], a2[2], a3[2];
#pragma unroll
        for (int mi = 0; mi < 2; ++mi) {
            const uint32_t row = (uint32_t)(warp_m * 32 + mi * 16) + a_row_in_warp;
            const uint32_t addr = Abase + row * 256 + bswz(row, kb + a_koff);
            ldm_x4(a0[mi], a1[mi], a2[mi], a3[mi], addr);
        }

        // ---- prefetch next table entry (consumed next k-step) ----
        uint4 qn;
        if (GATHER && k0 < 7) {
            qn = __ldg(tab + (k0 + 1) * 16 + warp);
        }

        // ---- 16 MMAs ----
#pragma unroll
        for (int mi = 0; mi < 2; ++mi) {
#pragma unroll
            for (int ni = 0; ni < 8; ++ni) {
                mma_16816(acc[mi][ni][0], acc[mi][ni][1],
                          acc[mi][ni][2], acc[mi][ni][3],
                          a0[mi], a1[mi], a2[mi], a3[mi],
                          bfr[ni][0], bfr[ni][1]);
            }
        }

        // ---- blend (half2) + store gathered pixel ----
        if (GATHER) {
            blend_store_h2(Anxt, u00, u10, u01, u11, q.z, q.w, k0 * 16 + warp, lane);
            q = qn;
        }
    }
}

// ---------------------------------------------------------------------------
// Kernel 2: fused gather+mma, 512 threads / 16 warps, warp tile 32x64 (R8)
// ---------------------------------------------------------------------------
__global__ __launch_bounds__(NTHREADS, 1)
void sphere_hmma_kernel(const float* __restrict__ bias,
                        float* __restrict__ out) {
    extern __shared__ char dsm[];
    const uint32_t raw = smem_u32(dsm);
    const uint32_t sb  = (raw + 1023u) & ~1023u;
    char* const smp = dsm + (sb - raw);

    const int tid  = threadIdx.x;
    const int lane = tid & 31;
    const int warp = tid >> 5;          // 0..15
    const int warp_m = warp >> 2;       // 0..3
    const int warp_n = warp & 3;        // 0..3
    const int tile = blockIdx.x;
    const int b    = tile >> 8;
    const int p0   = (tile & 255) * TILE_M;

    if (tid < 256) ((float*)(smp + SM_BIAS))[tid] = bias[tid];

    const uint2* __restrict__ xh2 =
        (const uint2*)(g_xh + (size_t)b * HW * CIN);

    float acc[2][8][4];
#pragma unroll
    for (int mi = 0; mi < 2; ++mi)
#pragma unroll
        for (int ni = 0; ni < 8; ++ni)
#pragma unroll
            for (int q = 0; q < 4; ++q) acc[mi][ni][q] = 0.0f;

    const uint32_t a_row_in_warp = (uint32_t)(lane & 15);
    const uint32_t a_koff        = (uint32_t)((lane >> 4) << 4);
    const uint32_t b_n_in_pair   = (uint32_t)(((lane >> 4) & 1) * 8 + (lane & 7));
    const uint32_t b_koff        = (uint32_t)(((lane >> 3) & 1) << 4);

    // ---- prologue: stage W(0); gather A(0) (table-driven, unfused) ----
    stageW_async(sb + SM_W0, g_Wf16, tid);
    cp_commit();
    {
        const uint4* __restrict__ tab = g_tab + p0;
#pragma unroll 2
        for (int i = 0; i < 8; ++i) {
            const int pp = i * 16 + warp;
            const uint4 q = __ldg(tab + pp);
            const uint2 u00 = __ldg(xh2 + (q.x & 0xFFFFu) * 32 + lane);
            const uint2 u10 = __ldg(xh2 + (q.x >> 16) * 32 + lane);
            const uint2 u01 = __ldg(xh2 + (q.y & 0xFFFFu) * 32 + lane);
            const uint2 u11 = __ldg(xh2 + (q.y >> 16) * 32 + lane);
            blend_store_h2(smp + SM_A0, u00, u10, u01, u11, q.z, q.w, pp, lane);
        }
    }
    cp_wait0();
    __syncthreads();

    for (int t = 0; t < 9; ++t) {
        const int cur = t & 1;
        const uint32_t Acur = sb + (cur ? SM_A1 : SM_A0);
        const uint32_t Wcur = sb + (cur ? SM_W1 : SM_W0);
        char* const Anxt = smp + (cur ? SM_A0 : SM_A1);
        const uint32_t Wnxt = sb + (cur ? SM_W0 : SM_W1);

        if (t < 8) {
            stageW_async(Wnxt, g_Wf16 + (size_t)(t + 1) * 65536, tid);
            cp_commit();
            mma_tap_fused<true>(Acur, Wcur, acc,
                                g_tab + (t + 1) * HW + p0,
                                xh2, Anxt,
                                a_row_in_warp, a_koff, b_n_in_pair, b_koff,
                                warp_m, warp_n, lane, warp);
            cp_wait0();
        } else {
            mma_tap_fused<false>(Acur, Wcur, acc, nullptr,
                                 xh2, nullptr,
                                 a_row_in_warp, a_koff, b_n_in_pair, b_koff,
                                 warp_m, warp_n, lane, warp);
        }
        __syncthreads();
    }

    // ---- epilogue: acc -> Dsm[co][px] (padded stride) -> coalesced out ----
    float* Dsm = (float*)smp;   // 256 x DSM_STRIDE fp32, conflict-free
    {
        const int rbase = warp_m * 32 + (lane >> 2);
        const int cbase = warp_n * 64 + 2 * (lane & 3);
#pragma unroll
        for (int mi = 0; mi < 2; ++mi) {
#pragma unroll
            for (int ni = 0; ni < 8; ++ni) {
                const int rr = rbase + mi * 16;
                const int cc = cbase + ni * 8;
                Dsm[(cc    ) * DSM_STRIDE + rr    ] = acc[mi][ni][0];
                Dsm[(cc + 1) * DSM_STRIDE + rr    ] = acc[mi][ni][1];
                Dsm[(cc    ) * DSM_STRIDE + rr + 8] = acc[mi][ni][2];
                Dsm[(cc + 1) * DSM_STRIDE + rr + 8] = acc[mi][ni][3];
            }
        }
    }
    __syncthreads();

    {
        const float* bs = (const float*)(smp + SM_BIAS);
        float* ob = out + (size_t)b * COUT * HW + p0;
#pragma unroll 4
        for (int it = 0; it < 16; ++it) {
            const int co = it * 16 + warp;
            const float bv = bs[co];
            float4 v = ((const float4*)(Dsm + co * DSM_STRIDE))[lane];
            v.x += bv; v.y += bv; v.z += bv; v.w += bv;
            ((float4*)(ob + (size_t)co * HW))[lane] = v;
        }
    }
}

// ---------------------------------------------------------------------------
extern "C" void kernel_launch(void* const* d_in, const int* in_sizes, int n_in,
                              void* d_out, int out_size) {
    const float* x      = (const float*)d_in[0];   // (4,128,128,256)
    const float* weight = (const float*)d_in[1];   // (256,128,3,3)
    const float* bias   = (const float*)d_in[2];   // (256,)
    const float* grid   = (const float*)d_in[3];   // (1,384,768,2)
    float* out = (float*)d_out;                    // (4,256,128,256)

    cudaFuncSetAttribute(sphere_hmma_kernel,
                         cudaFuncAttributeMaxDynamicSharedMemorySize, SM_TOTAL);

    prep_all_kernel<<<NBLK_TRANS + NBLK_PREP, 256>>>(x, weight, grid);
    sphere_hmma_kernel<<<NTILES, NTHREADS, SM_TOTAL>>>(bias, out);
}